// round 11
// baseline (speedup 1.0000x reference)
#include <cuda_runtime.h>
#include <cuda_fp16.h>
#include <math.h>
#include <stdint.h>

#define D_MODEL   256
#define NUM_HEADS 8
#define DIM_HEAD  32
#define S_LEN     4096
#define MAX_B     2
#define LN_EPS    1e-6f
#define FULL_MASK 0xffffffffu
#define QK_SCALE  0.2550565405694324f      // (1/sqrt(32)) * log2(e)

// f16 scratch stored as packed words.
__device__ uint32_t g_xh[MAX_B * S_LEN * D_MODEL / 2];        // [N][128w] f16 x
__device__ uint32_t g_wt[3 * D_MODEL * D_MODEL / 2];          // [z][n][128w] f16 W^T
__device__ uint32_t g_mh[MAX_B * S_LEN / 2];                  // f16x2 mask, [tile][qq][j]
__device__ uint32_t g_q[MAX_B * NUM_HEADS * S_LEN * DIM_HEAD / 2];
__device__ uint32_t g_k[MAX_B * NUM_HEADS * S_LEN * DIM_HEAD / 2];
__device__ uint32_t g_v[MAX_B * NUM_HEADS * S_LEN * DIM_HEAD / 2];
__device__ uint32_t g_o[MAX_B * NUM_HEADS * S_LEN * DIM_HEAD / 2];   // f16 O

// ---------------------------------------------------------------------------
// Helpers
// ---------------------------------------------------------------------------
__device__ __forceinline__ uint32_t pack_f16(float lo, float hi) {
    uint32_t r;
    asm("cvt.rn.f16x2.f32 %0, %1, %2;" : "=r"(r) : "f"(hi), "f"(lo));
    return r;
}
__device__ __forceinline__ uint32_t ex2_f16x2(uint32_t x) {
    uint32_t y;
    asm("ex2.approx.f16x2 %0, %1;" : "=r"(y) : "r"(x));
    return y;
}
__device__ __forceinline__ uint32_t hadd2(uint32_t a, uint32_t b) {
    uint32_t y;
    asm("add.rn.f16x2 %0, %1, %2;" : "=r"(y) : "r"(a), "r"(b));
    return y;
}
__device__ __forceinline__ float2 h2f2(uint32_t w) {
    __half2 h = *reinterpret_cast<__half2*>(&w);
    return __half22float2(h);
}
// f32-accum mma (QKV projection + PV)
__device__ __forceinline__ void mma_f16(float c[4],
                                        uint32_t a0, uint32_t a1, uint32_t a2, uint32_t a3,
                                        uint32_t b0, uint32_t b1) {
    asm volatile(
        "mma.sync.aligned.m16n8k16.row.col.f32.f16.f16.f32 "
        "{%0,%1,%2,%3},{%4,%5,%6,%7},{%8,%9},{%0,%1,%2,%3};"
        : "+f"(c[0]), "+f"(c[1]), "+f"(c[2]), "+f"(c[3])
        : "r"(a0), "r"(a1), "r"(a2), "r"(a3), "r"(b0), "r"(b1));
}
// f16-accum mma (scores): C/D are two f16x2 words
__device__ __forceinline__ void mma_f16h(uint32_t c[2],
                                         uint32_t a0, uint32_t a1, uint32_t a2, uint32_t a3,
                                         uint32_t b0, uint32_t b1) {
    asm volatile(
        "mma.sync.aligned.m16n8k16.row.col.f16.f16.f16.f16 "
        "{%0,%1},{%2,%3,%4,%5},{%6,%7},{%0,%1};"
        : "+r"(c[0]), "+r"(c[1])
        : "r"(a0), "r"(a1), "r"(a2), "r"(a3), "r"(b0), "r"(b1));
}
__device__ __forceinline__ void ldsm_x4(uint32_t& d0, uint32_t& d1,
                                        uint32_t& d2, uint32_t& d3, uint32_t addr) {
    asm volatile("ldmatrix.sync.aligned.m8n8.x4.shared.b16 {%0,%1,%2,%3}, [%4];"
                 : "=r"(d0), "=r"(d1), "=r"(d2), "=r"(d3) : "r"(addr));
}
__device__ __forceinline__ void cp16(uint32_t dst, const void* src) {
    asm volatile("cp.async.cg.shared.global [%0], [%1], 16;" :: "r"(dst), "l"(src));
}
__device__ __forceinline__ void cp_commit() {
    asm volatile("cp.async.commit_group;");
}
__device__ __forceinline__ void cp_wait0() {
    asm volatile("cp.async.wait_group 0;");
}
__device__ __forceinline__ void cp_wait1() {
    asm volatile("cp.async.wait_group 1;");
}
__device__ __forceinline__ void cp_wait2() {
    asm volatile("cp.async.wait_group 2;");
}

// ---------------------------------------------------------------------------
// Kernel 0: fp32 -> f16 conversion. x -> g_xh; W^T -> g_wt; mask -> g_mh.
// Mask stored permuted per 64-key tile: word index = qq*8 + j.
// ---------------------------------------------------------------------------
__global__ void convert_kernel(const float* __restrict__ x,
                               const float* __restrict__ Wq,
                               const float* __restrict__ Wk,
                               const float* __restrict__ Wv,
                               const float* __restrict__ pad,
                               int xblocks, int mwords) {
    const int bid = blockIdx.x;
    if (bid < xblocks) {
        const int j = bid * 256 + threadIdx.x;
        const float4 f0 = *reinterpret_cast<const float4*>(&x[j * 8]);
        const float4 f1 = *reinterpret_cast<const float4*>(&x[j * 8 + 4]);
        uint4 o;
        o.x = pack_f16(f0.x, f0.y); o.y = pack_f16(f0.z, f0.w);
        o.z = pack_f16(f1.x, f1.y); o.w = pack_f16(f1.z, f1.w);
        reinterpret_cast<uint4*>(g_xh)[j] = o;
    } else if (bid < xblocks + 384) {
        const int i  = (bid - xblocks) * 256 + threadIdx.x;
        const int n  = i & 255;
        const int kw = (i >> 8) & 127;
        const int z  = i >> 15;
        const float* W = (z == 0) ? Wq : (z == 1) ? Wk : Wv;
        const float a = W[(2 * kw    ) * D_MODEL + n];
        const float b = W[(2 * kw + 1) * D_MODEL + n];
        g_wt[z * 32768 + n * 128 + kw] = pack_f16(a, b);
    } else {
        const int w = (bid - xblocks - 384) * 256 + threadIdx.x;
        if (w < mwords) {
            const float2 m = *reinterpret_cast<const float2*>(&pad[w * 2]);
            const uint32_t lo = (m.x > 0.5f) ? 0xFC00u : 0u;
            const uint32_t hi = (m.y > 0.5f) ? 0xFC00u : 0u;
            const int tile = w >> 5;
            const int pair = w & 31;
            const int jj   = pair >> 2;
            const int qq2  = pair & 3;
            g_mh[tile * 32 + qq2 * 8 + jj] = lo | (hi << 16);
        }
    }
}

// ---------------------------------------------------------------------------
// Kernel 1: QKV projection, f16 mma, cp.async double-buffer, ldmatrix frags.
// grid = (N/128, 4, 3), block = 256 (8 warps: 4 m x 2 n).
// ---------------------------------------------------------------------------
#define AS_WORDS (128 * 36)
#define WS_WORDS (64 * 36)
#define QKV_SMEM ((2 * AS_WORDS + 2 * WS_WORDS) * 4)

__global__ void __launch_bounds__(256, 2)
qkv_mma_kernel(const float* __restrict__ bq, const float* __restrict__ bk,
               const float* __restrict__ bv) {
    extern __shared__ __align__(16) uint32_t dsm[];
    uint32_t* AsW = dsm;
    uint32_t* WsW = dsm + 2 * AS_WORDS;

    const int z = blockIdx.z;
    const float* bias = (z == 0) ? bq : (z == 1) ? bk : bv;

    const int row0 = blockIdx.x * 128;
    const int n0   = blockIdx.y * 64;
    const int tid  = threadIdx.x;
    const int warp = tid >> 5, lane = tid & 31;
    const int r    = lane >> 2, qq = lane & 3;
    const int wm   = warp >> 1;
    const int wn   = warp & 1;

    const uint32_t as_st = (uint32_t)__cvta_generic_to_shared(AsW);
    const uint32_t ws_st = (uint32_t)__cvta_generic_to_shared(WsW);
    const uint32_t AS_B = AS_WORDS * 4, WS_B = WS_WORDS * 4;

    const uint32_t* xsrc = g_xh + (size_t)row0 * 128;
    const uint32_t* wsrc = g_wt + z * 32768 + n0 * 128;

    auto issue_chunk = [&](int kc) {
        const int buf = kc & 1;
        #pragma unroll
        for (int i = 0; i < 4; i++) {
            const int idx = tid + i * 256;
            const int m = idx >> 3, q = idx & 7;
            cp16(as_st + buf * AS_B + (m * 36 + q * 4) * 4,
                 xsrc + m * 128 + kc * 32 + q * 4);
        }
        #pragma unroll
        for (int i = 0; i < 2; i++) {
            const int idx = tid + i * 256;
            const int n = idx >> 3, q = idx & 7;
            cp16(ws_st + buf * WS_B + (n * 36 + q * 4) * 4,
                 wsrc + n * 128 + kc * 32 + q * 4);
        }
        cp_commit();
    };

    float acc[2][4][4];
    #pragma unroll
    for (int mf = 0; mf < 2; mf++)
        #pragma unroll
        for (int nf = 0; nf < 4; nf++)
            #pragma unroll
            for (int i = 0; i < 4; i++) acc[mf][nf][i] = 0.f;

    const uint32_t a_lane = ((wm * 32 + (lane & 15)) * 36 + (lane >> 4) * 4) * 4;
    const uint32_t b_lane = ((wn * 32 + (lane & 15)) * 36 + (lane >> 4) * 4) * 4;

    issue_chunk(0);
    for (int kc = 0; kc < 4; kc++) {
        cp_wait0();
        __syncthreads();
        if (kc < 3) issue_chunk(kc + 1);

        const int buf = kc & 1;
        const uint32_t ab = as_st + buf * AS_B + a_lane;
        const uint32_t bb = ws_st + buf * WS_B + b_lane;
        #pragma unroll
        for (int ks = 0; ks < 4; ks++) {
            uint32_t a[2][4], bf[4][2];
            ldsm_x4(a[0][0], a[0][1], a[0][2], a[0][3], ab + ks * 32);
            ldsm_x4(a[1][0], a[1][1], a[1][2], a[1][3], ab + 16 * 36 * 4 + ks * 32);
            ldsm_x4(bf[0][0], bf[1][0], bf[0][1], bf[1][1], bb + ks * 32);
            ldsm_x4(bf[2][0], bf[3][0], bf[2][1], bf[3][1], bb + 16 * 36 * 4 + ks * 32);
            #pragma unroll
            for (int mf = 0; mf < 2; mf++)
                #pragma unroll
                for (int nf = 0; nf < 4; nf++)
                    mma_f16(acc[mf][nf], a[mf][0], a[mf][1], a[mf][2], a[mf][3],
                            bf[nf][0], bf[nf][1]);
        }
        if (kc < 3) __syncthreads();
    }

    const int b  = row0 >> 12;
    const int s0 = row0 & (S_LEN - 1);

    if (z != 2) {
        uint32_t* out = (z == 0) ? g_q : g_k;
        const float scale = (z == 0) ? QK_SCALE : 1.0f;
        const int h  = (n0 >> 5) + wn;
        const int bh = b * NUM_HEADS + h;
        #pragma unroll
        for (int mf = 0; mf < 2; mf++) {
            const int s = s0 + wm * 32 + mf * 16;
            #pragma unroll
            for (int nf = 0; nf < 4; nf++) {
                const float2 bb = *reinterpret_cast<const float2*>(
                    &bias[n0 + wn * 32 + nf * 8 + qq * 2]);
                const float c0 = (acc[mf][nf][0] + bb.x) * scale;
                const float c1 = (acc[mf][nf][1] + bb.y) * scale;
                const float c2 = (acc[mf][nf][2] + bb.x) * scale;
                const float c3 = (acc[mf][nf][3] + bb.y) * scale;
                out[((size_t)bh * S_LEN + s + r    ) * 16 + nf * 4 + qq] = pack_f16(c0, c1);
                out[((size_t)bh * S_LEN + s + r + 8) * 16 + nf * 4 + qq] = pack_f16(c2, c3);
            }
        }
    } else {
        __syncthreads();
        __half* Vt = reinterpret_cast<__half*>(dsm);   // [64 n][136 s]
        #pragma unroll
        for (int mf = 0; mf < 2; mf++) {
            const int ml = wm * 32 + mf * 16;
            #pragma unroll
            for (int nf = 0; nf < 4; nf++) {
                const int nc = wn * 32 + nf * 8 + qq * 2;
                const float2 bb = *reinterpret_cast<const float2*>(&bias[n0 + nc]);
                Vt[(nc    ) * 136 + ml + r    ] = __float2half(acc[mf][nf][0] + bb.x);
                Vt[(nc + 1) * 136 + ml + r    ] = __float2half(acc[mf][nf][1] + bb.y);
                Vt[(nc    ) * 136 + ml + r + 8] = __float2half(acc[mf][nf][2] + bb.x);
                Vt[(nc + 1) * 136 + ml + r + 8] = __float2half(acc[mf][nf][3] + bb.y);
            }
        }
        __syncthreads();
        #pragma unroll
        for (int i = 0; i < 4; i++) {
            const int idx = tid + i * 256;
            const int n = idx >> 4, wq = (idx & 15) * 4;
            const uint4 val = *reinterpret_cast<const uint4*>(&Vt[n * 136 + wq * 2]);
            const int col = n0 + n;
            const int bh  = b * NUM_HEADS + (col >> 5);
            const int dh  = col & 31;
            *reinterpret_cast<uint4*>(
                &g_v[((size_t)bh * DIM_HEAD + dh) * (S_LEN / 2) + (s0 >> 1) + wq]) = val;
        }
    }
}

// ---------------------------------------------------------------------------
// Kernel 2: flash attention, software-pipelined: per iteration computes
// scores(t+1)->P(t+1) AND PV(t) between the same barriers so tensor work of
// one tile overlaps MUFU softmax of the next. 4-buffer cp.async ring.
// grid = (S/128, H, B), block = 256 (8 warps, 16 q-rows each). BK = 64.
// ---------------------------------------------------------------------------
__global__ void __launch_bounds__(256, 2)
attn_mma_kernel() {
    __shared__ __align__(16) uint32_t Ks[4][64][20];
    __shared__ __align__(16) uint32_t Vs[4][32][36];
    __shared__ __align__(16) uint32_t Ms[4][32];     // f16x2 mask, [qq][j] order

    const int tid  = threadIdx.x;
    const int warp = tid >> 5;
    const int lane = tid & 31;
    const int r    = lane >> 2;
    const int qq   = lane & 3;

    const int qt = blockIdx.x, h = blockIdx.y, b = blockIdx.z;
    const int bh = b * NUM_HEADS + h;
    const int q0 = qt * 128 + warp * 16;

    const uint32_t ks_st = (uint32_t)__cvta_generic_to_shared(&Ks[0][0][0]);
    const uint32_t vs_st = (uint32_t)__cvta_generic_to_shared(&Vs[0][0][0]);
    const uint32_t ms_st = (uint32_t)__cvta_generic_to_shared(&Ms[0][0]);
    const uint32_t KS_B = 64 * 20 * 4, VS_B = 32 * 36 * 4;

    const uint32_t ks_lane = (uint32_t)__cvta_generic_to_shared(
        &Ks[0][lane & 7][(lane >> 3) * 4]);
    const uint32_t vs_lane = (uint32_t)__cvta_generic_to_shared(
        &Vs[0][lane & 7][(lane >> 3) * 4]);

    const uint32_t* Kw = g_k + (size_t)bh * S_LEN * 16;
    const uint32_t* Vw = g_v + (size_t)bh * DIM_HEAD * (S_LEN / 2);
    const uint32_t* Mw = g_mh + b * (S_LEN / 2);

    auto issue_tile = [&](int t) {
        const int buf = t & 3;
        cp16(ks_st + buf * KS_B + ((tid >> 2) * 20 + (tid & 3) * 4) * 4,
             Kw + t * 1024 + tid * 4);
        cp16(vs_st + buf * VS_B + ((tid >> 3) * 36 + (tid & 7) * 4) * 4,
             Vw + (tid >> 3) * (S_LEN / 2) + t * 32 + (tid & 7) * 4);
        if (tid < 8) cp16(ms_st + buf * 128 + tid * 16, Mw + t * 32 + tid * 4);
        cp_commit();
    };

    // Q fragments (pre-scaled by QK_SCALE)
    uint32_t qa[2][4];
    {
        const uint32_t* Qw = g_q + ((size_t)bh * S_LEN + q0) * 16;
        #pragma unroll
        for (int t = 0; t < 2; t++) {
            qa[t][0] = Qw[(r    ) * 16 + t * 8 + qq    ];
            qa[t][1] = Qw[(r + 8) * 16 + t * 8 + qq    ];
            qa[t][2] = Qw[(r    ) * 16 + t * 8 + qq + 4];
            qa[t][3] = Qw[(r + 8) * 16 + t * 8 + qq + 4];
        }
    }

    float oa[4][4];
    #pragma unroll
    for (int nn = 0; nn < 4; nn++)
        #pragma unroll
        for (int i = 0; i < 4; i++) oa[nn][i] = 0.f;
    float l0 = 0.f, l1 = 0.f;

    uint32_t pa[2][4][4];   // double-buffered P fragments

    // scores(tile t) -> pa[s], accumulate l
    auto scores_tile = [&](int t, int s) {
        const int p = t & 3;
        const uint32_t kaddr = ks_lane + (uint32_t)p * KS_B;
        const uint4 m03 = *reinterpret_cast<const uint4*>(&Ms[p][qq * 8]);
        const uint4 m47 = *reinterpret_cast<const uint4*>(&Ms[p][qq * 8 + 4]);
        const uint32_t mw[8] = {m03.x, m03.y, m03.z, m03.w,
                                m47.x, m47.y, m47.z, m47.w};
        #pragma unroll
        for (int j = 0; j < 8; j++) {
            uint32_t b00, b01, b10, b11;
            ldsm_x4(b00, b01, b10, b11, kaddr + j * (8 * 20 * 4));
            uint32_t sd[2] = {mw[j], mw[j]};
            mma_f16h(sd, qa[0][0], qa[0][1], qa[0][2], qa[0][3], b00, b01);
            mma_f16h(sd, qa[1][0], qa[1][1], qa[1][2], qa[1][3], b10, b11);
            pa[s][j >> 1][(j & 1) * 2    ] = ex2_f16x2(sd[0]);
            pa[s][j >> 1][(j & 1) * 2 + 1] = ex2_f16x2(sd[1]);
        }
        const uint32_t t0 = hadd2(
            hadd2(hadd2(pa[s][0][0], pa[s][0][2]), hadd2(pa[s][1][0], pa[s][1][2])),
            hadd2(hadd2(pa[s][2][0], pa[s][2][2]), hadd2(pa[s][3][0], pa[s][3][2])));
        const uint32_t t1 = hadd2(
            hadd2(hadd2(pa[s][0][1], pa[s][0][3]), hadd2(pa[s][1][1], pa[s][1][3])),
            hadd2(hadd2(pa[s][2][1], pa[s][2][3]), hadd2(pa[s][3][1], pa[s][3][3])));
        const float2 f0 = h2f2(t0);
        const float2 f1 = h2f2(t1);
        l0 += f0.x + f0.y;
        l1 += f1.x + f1.y;
    };

    // PV(tile t) using pa[s]
    auto pv_tile = [&](int t, int s) {
        const int p = t & 3;
        const uint32_t vaddr = vs_lane + (uint32_t)p * VS_B;
        #pragma unroll
        for (int nn = 0; nn < 4; nn++) {
            uint32_t vb[4][2];
            ldsm_x4(vb[0][0], vb[0][1], vb[1][0], vb[1][1],
                    vaddr + nn * (8 * 36 * 4));
            ldsm_x4(vb[2][0], vb[2][1], vb[3][0], vb[3][1],
                    vaddr + nn * (8 * 36 * 4) + 64);
            #pragma unroll
            for (int jp = 0; jp < 4; jp++)
                mma_f16(oa[nn], pa[s][jp][0], pa[s][jp][1], pa[s][jp][2], pa[s][jp][3],
                        vb[jp][0], vb[jp][1]);
        }
    };

    const int NT = S_LEN / 64;   // 64 tiles

    // prologue: 3 tiles in flight; compute P(0)
    issue_tile(0);
    issue_tile(1);
    issue_tile(2);
    cp_wait2();
    __syncthreads();
    scores_tile(0, 0);

    for (int t = 0; t < NT - 1; t++) {
        if (t < NT - 2) cp_wait1(); else cp_wait0();   // tile t+1 resident
        __syncthreads();
        if (t + 3 < NT) issue_tile(t + 3);
        scores_tile(t + 1, (t + 1) & 1);   // MUFU/tensor of next tile ...
        pv_tile(t, t & 1);                 // ... overlaps PV tensor of this one
    }
    pv_tile(NT - 1, (NT - 1) & 1);

    // quad reduction: full row sums
    l0 += __shfl_xor_sync(FULL_MASK, l0, 1);
    l0 += __shfl_xor_sync(FULL_MASK, l0, 2);
    l1 += __shfl_xor_sync(FULL_MASK, l1, 1);
    l1 += __shfl_xor_sync(FULL_MASK, l1, 2);
    const float i0 = 1.0f / l0;
    const float i1 = 1.0f / l1;

    // f16 O epilogue: [bh][s][16 words]
    uint32_t* Op = g_o + ((size_t)bh * S_LEN + q0) * 16;
    #pragma unroll
    for (int nn = 0; nn < 4; nn++) {
        Op[(r    ) * 16 + nn * 4 + qq] = pack_f16(oa[nn][0] * i0, oa[nn][1] * i0);
        Op[(r + 8) * 16 + nn * 4 + qq] = pack_f16(oa[nn][2] * i1, oa[nn][3] * i1);
    }
}

// ---------------------------------------------------------------------------
// Kernel 3: residual + LayerNorm, warp-per-row, f16 O input.
// ---------------------------------------------------------------------------
__global__ void ln_kernel(const float* __restrict__ x,
                          const float* __restrict__ gamma,
                          const float* __restrict__ beta,
                          float* __restrict__ out) {
    const int warp = threadIdx.x >> 5;
    const int lane = threadIdx.x & 31;
    const int row  = blockIdx.x * 8 + warp;
    const int b    = row >> 12;
    const int s    = row & (S_LEN - 1);

    const int d0 = lane * 8;
    const int bh = b * NUM_HEADS + (d0 >> 5);
    const uint32_t* Oq = &g_o[((size_t)bh * S_LEN + s) * 16 + (lane & 3) * 4];
    const float* Xq = &x[(size_t)row * D_MODEL + d0];

    float v[8];
    {
        const uint4 aw = *reinterpret_cast<const uint4*>(Oq);
        const float2 a0 = __half22float2(*reinterpret_cast<const __half2*>(&aw.x));
        const float2 a1 = __half22float2(*reinterpret_cast<const __half2*>(&aw.y));
        const float2 a2 = __half22float2(*reinterpret_cast<const __half2*>(&aw.z));
        const float2 a3 = __half22float2(*reinterpret_cast<const __half2*>(&aw.w));
        const float4 x0 = *reinterpret_cast<const float4*>(Xq);
        const float4 x1 = *reinterpret_cast<const float4*>(Xq + 4);
        v[0] = a0.x + x0.x; v[1] = a0.y + x0.y; v[2] = a1.x + x0.z; v[3] = a1.y + x0.w;
        v[4] = a2.x + x1.x; v[5] = a2.y + x1.y; v[6] = a3.x + x1.z; v[7] = a3.y + x1.w;
    }

    float sum = 0.f, sq = 0.f;
    #pragma unroll
    for (int i = 0; i < 8; i++) { sum += v[i]; sq += v[i] * v[i]; }
    #pragma unroll
    for (int off = 16; off > 0; off >>= 1) {
        sum += __shfl_xor_sync(FULL_MASK, sum, off);
        sq  += __shfl_xor_sync(FULL_MASK, sq,  off);
    }
    const float mu  = sum * (1.0f / D_MODEL);
    const float var = sq * (1.0f / D_MODEL) - mu * mu;
    const float rs  = rsqrtf(var + LN_EPS);

    const float4 g0 = *reinterpret_cast<const float4*>(&gamma[d0]);
    const float4 g1 = *reinterpret_cast<const float4*>(&gamma[d0 + 4]);
    const float4 b0 = *reinterpret_cast<const float4*>(&beta[d0]);
    const float4 b1 = *reinterpret_cast<const float4*>(&beta[d0 + 4]);

    float4 o0, o1;
    o0.x = g0.x * (v[0] - mu) * rs + b0.x;
    o0.y = g0.y * (v[1] - mu) * rs + b0.y;
    o0.z = g0.z * (v[2] - mu) * rs + b0.z;
    o0.w = g0.w * (v[3] - mu) * rs + b0.w;
    o1.x = g1.x * (v[4] - mu) * rs + b1.x;
    o1.y = g1.y * (v[5] - mu) * rs + b1.y;
    o1.z = g1.z * (v[6] - mu) * rs + b1.z;
    o1.w = g1.w * (v[7] - mu) * rs + b1.w;
    *reinterpret_cast<float4*>(&out[(size_t)row * D_MODEL + d0])     = o0;
    *reinterpret_cast<float4*>(&out[(size_t)row * D_MODEL + d0 + 4]) = o1;
}

// ---------------------------------------------------------------------------
// Launch
// ---------------------------------------------------------------------------
extern "C" void kernel_launch(void* const* d_in, const int* in_sizes, int n_in,
                              void* d_out, int out_size) {
    const float* x     = (const float*)d_in[0];
    const float* pad   = (const float*)d_in[1];
    const float* Wq    = (const float*)d_in[2];
    const float* bq    = (const float*)d_in[3];
    const float* Wk    = (const float*)d_in[4];
    const float* bk    = (const float*)d_in[5];
    const float* Wv    = (const float*)d_in[6];
    const float* bv    = (const float*)d_in[7];
    const float* gamma = (const float*)d_in[8];
    const float* beta  = (const float*)d_in[9];

    const int N = in_sizes[1];            // pad_mask [B,S] -> N = B*S rows
    const int B = N / S_LEN;
    const int xblocks = N * (D_MODEL / 8) / 256;
    const int mwords  = N / 2;
    const int mblocks = (mwords + 255) / 256;

    static bool attr_set = false;
    if (!attr_set) {
        cudaFuncSetAttribute(qkv_mma_kernel,
                             cudaFuncAttributeMaxDynamicSharedMemorySize, QKV_SMEM);
        attr_set = true;
    }

    convert_kernel<<<xblocks + 384 + mblocks, 256>>>(x, Wq, Wk, Wv, pad, xblocks, mwords);
    qkv_mma_kernel<<<dim3(N / 128, 4, 3), 256, QKV_SMEM>>>(bq, bk, bv);
    attn_mma_kernel<<<dim3(S_LEN / 128, NUM_HEADS, B), 256>>>();
    ln_kernel<<<N / 8, 256>>>(x, gamma, beta, (float*)d_out);
}

// round 13
// speedup vs baseline: 1.1576x; 1.1576x over previous
#include <cuda_runtime.h>
#include <cuda_fp16.h>
#include <math.h>
#include <stdint.h>

#define D_MODEL   256
#define NUM_HEADS 8
#define DIM_HEAD  32
#define S_LEN     4096
#define MAX_B     2
#define LN_EPS    1e-6f
#define FULL_MASK 0xffffffffu
#define QK_SCALE  0.2550565405694324f      // (1/sqrt(32)) * log2(e)

// f16 scratch stored as packed words.
__device__ uint32_t g_xh[MAX_B * S_LEN * D_MODEL / 2];        // [N][128w] f16 x
__device__ uint32_t g_wt[3 * D_MODEL * D_MODEL / 2];          // [z][n][128w] f16 W^T
__device__ uint32_t g_mh[MAX_B * S_LEN / 2];                  // f16x2 mask, [tile][qq][j]
__device__ uint32_t g_q[MAX_B * NUM_HEADS * S_LEN * DIM_HEAD / 2];
__device__ uint32_t g_k[MAX_B * NUM_HEADS * S_LEN * DIM_HEAD / 2];
__device__ uint32_t g_v[MAX_B * NUM_HEADS * S_LEN * DIM_HEAD / 2];
__device__ uint32_t g_o[MAX_B * NUM_HEADS * S_LEN * DIM_HEAD / 2];   // f16 O

// ---------------------------------------------------------------------------
// Helpers
// ---------------------------------------------------------------------------
__device__ __forceinline__ uint32_t pack_f16(float lo, float hi) {
    uint32_t r;
    asm("cvt.rn.f16x2.f32 %0, %1, %2;" : "=r"(r) : "f"(hi), "f"(lo));
    return r;
}
__device__ __forceinline__ uint32_t ex2_f16x2(uint32_t x) {
    uint32_t y;
    asm("ex2.approx.f16x2 %0, %1;" : "=r"(y) : "r"(x));
    return y;
}
__device__ __forceinline__ uint32_t hadd2(uint32_t a, uint32_t b) {
    uint32_t y;
    asm("add.rn.f16x2 %0, %1, %2;" : "=r"(y) : "r"(a), "r"(b));
    return y;
}
__device__ __forceinline__ float2 h2f2(uint32_t w) {
    __half2 h = *reinterpret_cast<__half2*>(&w);
    return __half22float2(h);
}
// f32-accum mma (QKV projection + PV)
__device__ __forceinline__ void mma_f16(float c[4],
                                        uint32_t a0, uint32_t a1, uint32_t a2, uint32_t a3,
                                        uint32_t b0, uint32_t b1) {
    asm volatile(
        "mma.sync.aligned.m16n8k16.row.col.f32.f16.f16.f32 "
        "{%0,%1,%2,%3},{%4,%5,%6,%7},{%8,%9},{%0,%1,%2,%3};"
        : "+f"(c[0]), "+f"(c[1]), "+f"(c[2]), "+f"(c[3])
        : "r"(a0), "r"(a1), "r"(a2), "r"(a3), "r"(b0), "r"(b1));
}
// f16-accum mma (scores): C/D are two f16x2 words
__device__ __forceinline__ void mma_f16h(uint32_t c[2],
                                         uint32_t a0, uint32_t a1, uint32_t a2, uint32_t a3,
                                         uint32_t b0, uint32_t b1) {
    asm volatile(
        "mma.sync.aligned.m16n8k16.row.col.f16.f16.f16.f16 "
        "{%0,%1},{%2,%3,%4,%5},{%6,%7},{%0,%1};"
        : "+r"(c[0]), "+r"(c[1])
        : "r"(a0), "r"(a1), "r"(a2), "r"(a3), "r"(b0), "r"(b1));
}
__device__ __forceinline__ void ldsm_x4(uint32_t& d0, uint32_t& d1,
                                        uint32_t& d2, uint32_t& d3, uint32_t addr) {
    asm volatile("ldmatrix.sync.aligned.m8n8.x4.shared.b16 {%0,%1,%2,%3}, [%4];"
                 : "=r"(d0), "=r"(d1), "=r"(d2), "=r"(d3) : "r"(addr));
}
__device__ __forceinline__ void cp16(uint32_t dst, const void* src) {
    asm volatile("cp.async.cg.shared.global [%0], [%1], 16;" :: "r"(dst), "l"(src));
}
__device__ __forceinline__ void cp_commit() {
    asm volatile("cp.async.commit_group;");
}
__device__ __forceinline__ void cp_wait0() {
    asm volatile("cp.async.wait_group 0;");
}
__device__ __forceinline__ void cp_wait1() {
    asm volatile("cp.async.wait_group 1;");
}

// ---------------------------------------------------------------------------
// Kernel 0: fp32 -> f16 conversion. x -> g_xh; W^T -> g_wt; mask -> g_mh.
// Mask stored permuted per 64-key tile: word index = qq*8 + j.
// ---------------------------------------------------------------------------
__global__ void convert_kernel(const float* __restrict__ x,
                               const float* __restrict__ Wq,
                               const float* __restrict__ Wk,
                               const float* __restrict__ Wv,
                               const float* __restrict__ pad,
                               int xblocks, int mwords) {
    const int bid = blockIdx.x;
    if (bid < xblocks) {
        const int j = bid * 256 + threadIdx.x;
        const float4 f0 = *reinterpret_cast<const float4*>(&x[j * 8]);
        const float4 f1 = *reinterpret_cast<const float4*>(&x[j * 8 + 4]);
        uint4 o;
        o.x = pack_f16(f0.x, f0.y); o.y = pack_f16(f0.z, f0.w);
        o.z = pack_f16(f1.x, f1.y); o.w = pack_f16(f1.z, f1.w);
        reinterpret_cast<uint4*>(g_xh)[j] = o;
    } else if (bid < xblocks + 384) {
        const int i  = (bid - xblocks) * 256 + threadIdx.x;
        const int n  = i & 255;
        const int kw = (i >> 8) & 127;
        const int z  = i >> 15;
        const float* W = (z == 0) ? Wq : (z == 1) ? Wk : Wv;
        const float a = W[(2 * kw    ) * D_MODEL + n];
        const float b = W[(2 * kw + 1) * D_MODEL + n];
        g_wt[z * 32768 + n * 128 + kw] = pack_f16(a, b);
    } else {
        const int w = (bid - xblocks - 384) * 256 + threadIdx.x;
        if (w < mwords) {
            const float2 m = *reinterpret_cast<const float2*>(&pad[w * 2]);
            const uint32_t lo = (m.x > 0.5f) ? 0xFC00u : 0u;
            const uint32_t hi = (m.y > 0.5f) ? 0xFC00u : 0u;
            const int tile = w >> 5;
            const int pair = w & 31;
            const int jj   = pair >> 2;
            const int qq2  = pair & 3;
            g_mh[tile * 32 + qq2 * 8 + jj] = lo | (hi << 16);
        }
    }
}

// ---------------------------------------------------------------------------
// Kernel 1: QKV projection, f16 mma, cp.async double-buffer, ldmatrix frags.
// grid = (N/128, 4, 3), block = 256 (8 warps: 4 m x 2 n).
// ---------------------------------------------------------------------------
#define AS_WORDS (128 * 36)
#define WS_WORDS (64 * 36)
#define QKV_SMEM ((2 * AS_WORDS + 2 * WS_WORDS) * 4)

__global__ void __launch_bounds__(256, 2)
qkv_mma_kernel(const float* __restrict__ bq, const float* __restrict__ bk,
               const float* __restrict__ bv) {
    extern __shared__ __align__(16) uint32_t dsm[];
    uint32_t* AsW = dsm;
    uint32_t* WsW = dsm + 2 * AS_WORDS;

    const int z = blockIdx.z;
    const float* bias = (z == 0) ? bq : (z == 1) ? bk : bv;

    const int row0 = blockIdx.x * 128;
    const int n0   = blockIdx.y * 64;
    const int tid  = threadIdx.x;
    const int warp = tid >> 5, lane = tid & 31;
    const int r    = lane >> 2, qq = lane & 3;
    const int wm   = warp >> 1;
    const int wn   = warp & 1;

    const uint32_t as_st = (uint32_t)__cvta_generic_to_shared(AsW);
    const uint32_t ws_st = (uint32_t)__cvta_generic_to_shared(WsW);
    const uint32_t AS_B = AS_WORDS * 4, WS_B = WS_WORDS * 4;

    const uint32_t* xsrc = g_xh + (size_t)row0 * 128;
    const uint32_t* wsrc = g_wt + z * 32768 + n0 * 128;

    auto issue_chunk = [&](int kc) {
        const int buf = kc & 1;
        #pragma unroll
        for (int i = 0; i < 4; i++) {
            const int idx = tid + i * 256;
            const int m = idx >> 3, q = idx & 7;
            cp16(as_st + buf * AS_B + (m * 36 + q * 4) * 4,
                 xsrc + m * 128 + kc * 32 + q * 4);
        }
        #pragma unroll
        for (int i = 0; i < 2; i++) {
            const int idx = tid + i * 256;
            const int n = idx >> 3, q = idx & 7;
            cp16(ws_st + buf * WS_B + (n * 36 + q * 4) * 4,
                 wsrc + n * 128 + kc * 32 + q * 4);
        }
        cp_commit();
    };

    float acc[2][4][4];
    #pragma unroll
    for (int mf = 0; mf < 2; mf++)
        #pragma unroll
        for (int nf = 0; nf < 4; nf++)
            #pragma unroll
            for (int i = 0; i < 4; i++) acc[mf][nf][i] = 0.f;

    const uint32_t a_lane = ((wm * 32 + (lane & 15)) * 36 + (lane >> 4) * 4) * 4;
    const uint32_t b_lane = ((wn * 32 + (lane & 15)) * 36 + (lane >> 4) * 4) * 4;

    issue_chunk(0);
    for (int kc = 0; kc < 4; kc++) {
        cp_wait0();
        __syncthreads();
        if (kc < 3) issue_chunk(kc + 1);

        const int buf = kc & 1;
        const uint32_t ab = as_st + buf * AS_B + a_lane;
        const uint32_t bb = ws_st + buf * WS_B + b_lane;
        #pragma unroll
        for (int ks = 0; ks < 4; ks++) {
            uint32_t a[2][4], bf[4][2];
            ldsm_x4(a[0][0], a[0][1], a[0][2], a[0][3], ab + ks * 32);
            ldsm_x4(a[1][0], a[1][1], a[1][2], a[1][3], ab + 16 * 36 * 4 + ks * 32);
            ldsm_x4(bf[0][0], bf[1][0], bf[0][1], bf[1][1], bb + ks * 32);
            ldsm_x4(bf[2][0], bf[3][0], bf[2][1], bf[3][1], bb + 16 * 36 * 4 + ks * 32);
            #pragma unroll
            for (int mf = 0; mf < 2; mf++)
                #pragma unroll
                for (int nf = 0; nf < 4; nf++)
                    mma_f16(acc[mf][nf], a[mf][0], a[mf][1], a[mf][2], a[mf][3],
                            bf[nf][0], bf[nf][1]);
        }
        if (kc < 3) __syncthreads();
    }

    const int b  = row0 >> 12;
    const int s0 = row0 & (S_LEN - 1);

    if (z != 2) {
        uint32_t* out = (z == 0) ? g_q : g_k;
        const float scale = (z == 0) ? QK_SCALE : 1.0f;
        const int h  = (n0 >> 5) + wn;
        const int bh = b * NUM_HEADS + h;
        #pragma unroll
        for (int mf = 0; mf < 2; mf++) {
            const int s = s0 + wm * 32 + mf * 16;
            #pragma unroll
            for (int nf = 0; nf < 4; nf++) {
                const float2 bb = *reinterpret_cast<const float2*>(
                    &bias[n0 + wn * 32 + nf * 8 + qq * 2]);
                const float c0 = (acc[mf][nf][0] + bb.x) * scale;
                const float c1 = (acc[mf][nf][1] + bb.y) * scale;
                const float c2 = (acc[mf][nf][2] + bb.x) * scale;
                const float c3 = (acc[mf][nf][3] + bb.y) * scale;
                out[((size_t)bh * S_LEN + s + r    ) * 16 + nf * 4 + qq] = pack_f16(c0, c1);
                out[((size_t)bh * S_LEN + s + r + 8) * 16 + nf * 4 + qq] = pack_f16(c2, c3);
            }
        }
    } else {
        __syncthreads();
        __half* Vt = reinterpret_cast<__half*>(dsm);   // [64 n][136 s]
        #pragma unroll
        for (int mf = 0; mf < 2; mf++) {
            const int ml = wm * 32 + mf * 16;
            #pragma unroll
            for (int nf = 0; nf < 4; nf++) {
                const int nc = wn * 32 + nf * 8 + qq * 2;
                const float2 bb = *reinterpret_cast<const float2*>(&bias[n0 + nc]);
                Vt[(nc    ) * 136 + ml + r    ] = __float2half(acc[mf][nf][0] + bb.x);
                Vt[(nc + 1) * 136 + ml + r    ] = __float2half(acc[mf][nf][1] + bb.y);
                Vt[(nc    ) * 136 + ml + r + 8] = __float2half(acc[mf][nf][2] + bb.x);
                Vt[(nc + 1) * 136 + ml + r + 8] = __float2half(acc[mf][nf][3] + bb.y);
            }
        }
        __syncthreads();
        #pragma unroll
        for (int i = 0; i < 4; i++) {
            const int idx = tid + i * 256;
            const int n = idx >> 4, wq = (idx & 15) * 4;
            const uint4 val = *reinterpret_cast<const uint4*>(&Vt[n * 136 + wq * 2]);
            const int col = n0 + n;
            const int bh  = b * NUM_HEADS + (col >> 5);
            const int dh  = col & 31;
            *reinterpret_cast<uint4*>(
                &g_v[((size_t)bh * DIM_HEAD + dh) * (S_LEN / 2) + (s0 >> 1) + wq]) = val;
        }
    }
}

// ---------------------------------------------------------------------------
// Kernel 2: flash attention, 32 q-rows per warp (BQ=256): each K/V ldsm
// result feeds TWO m-fragments -> smem read traffic per q halved; grid is
// exactly one wave (256 blocks @ occ 2). 3-stage cp.async ring, 1 barrier/tile.
// grid = (S/256, H, B), block = 256 (8 warps).
// ---------------------------------------------------------------------------
__global__ void __launch_bounds__(256, 2)
attn_mma_kernel() {
    __shared__ __align__(16) uint32_t Ks[3][64][20];
    __shared__ __align__(16) uint32_t Vs[3][32][36];
    __shared__ __align__(16) uint32_t Ms[3][32];     // f16x2 mask, [qq][j] order

    const int tid  = threadIdx.x;
    const int warp = tid >> 5;
    const int lane = tid & 31;
    const int r    = lane >> 2;
    const int qq   = lane & 3;

    const int qt = blockIdx.x, h = blockIdx.y, b = blockIdx.z;
    const int bh = b * NUM_HEADS + h;
    const int q0 = qt * 256 + warp * 32;

    const uint32_t ks_st = (uint32_t)__cvta_generic_to_shared(&Ks[0][0][0]);
    const uint32_t vs_st = (uint32_t)__cvta_generic_to_shared(&Vs[0][0][0]);
    const uint32_t ms_st = (uint32_t)__cvta_generic_to_shared(&Ms[0][0]);
    const uint32_t KS_B = 64 * 20 * 4, VS_B = 32 * 36 * 4;

    const uint32_t ks_lane = (uint32_t)__cvta_generic_to_shared(
        &Ks[0][lane & 7][(lane >> 3) * 4]);
    const uint32_t vs_lane = (uint32_t)__cvta_generic_to_shared(
        &Vs[0][lane & 7][(lane >> 3) * 4]);

    const uint32_t* Kw = g_k + (size_t)bh * S_LEN * 16;
    const uint32_t* Vw = g_v + (size_t)bh * DIM_HEAD * (S_LEN / 2);
    const uint32_t* Mw = g_mh + b * (S_LEN / 2);

    auto issue_tile = [&](int t) {
        const int buf = t % 3;
        cp16(ks_st + buf * KS_B + ((tid >> 2) * 20 + (tid & 3) * 4) * 4,
             Kw + t * 1024 + tid * 4);
        cp16(vs_st + buf * VS_B + ((tid >> 3) * 36 + (tid & 7) * 4) * 4,
             Vw + (tid >> 3) * (S_LEN / 2) + t * 32 + (tid & 7) * 4);
        if (tid < 8) cp16(ms_st + buf * 128 + tid * 16, Mw + t * 32 + tid * 4);
        cp_commit();
    };

    // Q fragments: 2 m-frags (rows q0+mf*16), 2 k-chunks each (pre-scaled)
    uint32_t qa[2][2][4];
    {
        const uint32_t* Qw = g_q + ((size_t)bh * S_LEN + q0) * 16;
        #pragma unroll
        for (int mf = 0; mf < 2; mf++)
            #pragma unroll
            for (int t = 0; t < 2; t++) {
                qa[mf][t][0] = Qw[(mf * 16 + r    ) * 16 + t * 8 + qq    ];
                qa[mf][t][1] = Qw[(mf * 16 + r + 8) * 16 + t * 8 + qq    ];
                qa[mf][t][2] = Qw[(mf * 16 + r    ) * 16 + t * 8 + qq + 4];
                qa[mf][t][3] = Qw[(mf * 16 + r + 8) * 16 + t * 8 + qq + 4];
            }
    }

    float oa[2][4][4];
    #pragma unroll
    for (int mf = 0; mf < 2; mf++)
        #pragma unroll
        for (int nn = 0; nn < 4; nn++)
            #pragma unroll
            for (int i = 0; i < 4; i++) oa[mf][nn][i] = 0.f;
    float l[2][2] = {{0.f, 0.f}, {0.f, 0.f}};

    issue_tile(0);
    issue_tile(1);

    for (int kt = 0; kt < S_LEN / 64; kt++) {
        if (kt < S_LEN / 64 - 1) cp_wait1(); else cp_wait0();
        __syncthreads();
        if (kt + 2 < S_LEN / 64) issue_tile(kt + 2);

        const int p = kt % 3;
        const uint32_t kaddr = ks_lane + (uint32_t)p * KS_B;
        const uint32_t vaddr = vs_lane + (uint32_t)p * VS_B;

        const uint4 m03 = *reinterpret_cast<const uint4*>(&Ms[p][qq * 8]);
        const uint4 m47 = *reinterpret_cast<const uint4*>(&Ms[p][qq * 8 + 4]);
        const uint32_t mw[8] = {m03.x, m03.y, m03.z, m03.w,
                                m47.x, m47.y, m47.z, m47.w};

        // ---- scores: each K ldsm feeds BOTH m-frags ----
        uint32_t pa[2][4][4];
        #pragma unroll
        for (int j = 0; j < 8; j++) {
            uint32_t b00, b01, b10, b11;
            ldsm_x4(b00, b01, b10, b11, kaddr + j * (8 * 20 * 4));
            #pragma unroll
            for (int mf = 0; mf < 2; mf++) {
                uint32_t sd[2] = {mw[j], mw[j]};
                mma_f16h(sd, qa[mf][0][0], qa[mf][0][1], qa[mf][0][2], qa[mf][0][3], b00, b01);
                mma_f16h(sd, qa[mf][1][0], qa[mf][1][1], qa[mf][1][2], qa[mf][1][3], b10, b11);
                pa[mf][j >> 1][(j & 1) * 2    ] = ex2_f16x2(sd[0]);
                pa[mf][j >> 1][(j & 1) * 2 + 1] = ex2_f16x2(sd[1]);
            }
        }

        // ---- l: hadd2 trees, f32 accumulate ----
        #pragma unroll
        for (int mf = 0; mf < 2; mf++) {
            const uint32_t t0 = hadd2(
                hadd2(hadd2(pa[mf][0][0], pa[mf][0][2]), hadd2(pa[mf][1][0], pa[mf][1][2])),
                hadd2(hadd2(pa[mf][2][0], pa[mf][2][2]), hadd2(pa[mf][3][0], pa[mf][3][2])));
            const uint32_t t1 = hadd2(
                hadd2(hadd2(pa[mf][0][1], pa[mf][0][3]), hadd2(pa[mf][1][1], pa[mf][1][3])),
                hadd2(hadd2(pa[mf][2][1], pa[mf][2][3]), hadd2(pa[mf][3][1], pa[mf][3][3])));
            const float2 f0 = h2f2(t0);
            const float2 f1 = h2f2(t1);
            l[mf][0] += f0.x + f0.y;
            l[mf][1] += f1.x + f1.y;
        }

        // ---- PV: each V ldsm feeds BOTH m-frags ----
        #pragma unroll
        for (int nn = 0; nn < 4; nn++) {
            uint32_t vb[4][2];
            ldsm_x4(vb[0][0], vb[0][1], vb[1][0], vb[1][1],
                    vaddr + nn * (8 * 36 * 4));
            ldsm_x4(vb[2][0], vb[2][1], vb[3][0], vb[3][1],
                    vaddr + nn * (8 * 36 * 4) + 64);
            #pragma unroll
            for (int mf = 0; mf < 2; mf++)
                #pragma unroll
                for (int jp = 0; jp < 4; jp++)
                    mma_f16(oa[mf][nn], pa[mf][jp][0], pa[mf][jp][1],
                            pa[mf][jp][2], pa[mf][jp][3], vb[jp][0], vb[jp][1]);
        }
    }

    // quad reductions + store
    uint32_t* Op = g_o + ((size_t)bh * S_LEN + q0) * 16;
    #pragma unroll
    for (int mf = 0; mf < 2; mf++) {
        float l0 = l[mf][0], l1 = l[mf][1];
        l0 += __shfl_xor_sync(FULL_MASK, l0, 1);
        l0 += __shfl_xor_sync(FULL_MASK, l0, 2);
        l1 += __shfl_xor_sync(FULL_MASK, l1, 1);
        l1 += __shfl_xor_sync(FULL_MASK, l1, 2);
        const float i0 = 1.0f / l0;
        const float i1 = 1.0f / l1;
        #pragma unroll
        for (int nn = 0; nn < 4; nn++) {
            Op[(mf * 16 + r    ) * 16 + nn * 4 + qq] =
                pack_f16(oa[mf][nn][0] * i0, oa[mf][nn][1] * i0);
            Op[(mf * 16 + r + 8) * 16 + nn * 4 + qq] =
                pack_f16(oa[mf][nn][2] * i1, oa[mf][nn][3] * i1);
        }
    }
}

// ---------------------------------------------------------------------------
// Kernel 3: residual + LayerNorm, warp-per-row, f16 O input.
// ---------------------------------------------------------------------------
__global__ void ln_kernel(const float* __restrict__ x,
                          const float* __restrict__ gamma,
                          const float* __restrict__ beta,
                          float* __restrict__ out) {
    const int warp = threadIdx.x >> 5;
    const int lane = threadIdx.x & 31;
    const int row  = blockIdx.x * 8 + warp;
    const int b    = row >> 12;
    const int s    = row & (S_LEN - 1);

    const int d0 = lane * 8;
    const int bh = b * NUM_HEADS + (d0 >> 5);
    const uint32_t* Oq = &g_o[((size_t)bh * S_LEN + s) * 16 + (lane & 3) * 4];
    const float* Xq = &x[(size_t)row * D_MODEL + d0];

    float v[8];
    {
        const uint4 aw = *reinterpret_cast<const uint4*>(Oq);
        const float2 a0 = __half22float2(*reinterpret_cast<const __half2*>(&aw.x));
        const float2 a1 = __half22float2(*reinterpret_cast<const __half2*>(&aw.y));
        const float2 a2 = __half22float2(*reinterpret_cast<const __half2*>(&aw.z));
        const float2 a3 = __half22float2(*reinterpret_cast<const __half2*>(&aw.w));
        const float4 x0 = *reinterpret_cast<const float4*>(Xq);
        const float4 x1 = *reinterpret_cast<const float4*>(Xq + 4);
        v[0] = a0.x + x0.x; v[1] = a0.y + x0.y; v[2] = a1.x + x0.z; v[3] = a1.y + x0.w;
        v[4] = a2.x + x1.x; v[5] = a2.y + x1.y; v[6] = a3.x + x1.z; v[7] = a3.y + x1.w;
    }

    float sum = 0.f, sq = 0.f;
    #pragma unroll
    for (int i = 0; i < 8; i++) { sum += v[i]; sq += v[i] * v[i]; }
    #pragma unroll
    for (int off = 16; off > 0; off >>= 1) {
        sum += __shfl_xor_sync(FULL_MASK, sum, off);
        sq  += __shfl_xor_sync(FULL_MASK, sq,  off);
    }
    const float mu  = sum * (1.0f / D_MODEL);
    const float var = sq * (1.0f / D_MODEL) - mu * mu;
    const float rs  = rsqrtf(var + LN_EPS);

    const float4 g0 = *reinterpret_cast<const float4*>(&gamma[d0]);
    const float4 g1 = *reinterpret_cast<const float4*>(&gamma[d0 + 4]);
    const float4 b0 = *reinterpret_cast<const float4*>(&beta[d0]);
    const float4 b1 = *reinterpret_cast<const float4*>(&beta[d0 + 4]);

    float4 o0, o1;
    o0.x = g0.x * (v[0] - mu) * rs + b0.x;
    o0.y = g0.y * (v[1] - mu) * rs + b0.y;
    o0.z = g0.z * (v[2] - mu) * rs + b0.z;
    o0.w = g0.w * (v[3] - mu) * rs + b0.w;
    o1.x = g1.x * (v[4] - mu) * rs + b1.x;
    o1.y = g1.y * (v[5] - mu) * rs + b1.y;
    o1.z = g1.z * (v[6] - mu) * rs + b1.z;
    o1.w = g1.w * (v[7] - mu) * rs + b1.w;
    *reinterpret_cast<float4*>(&out[(size_t)row * D_MODEL + d0])     = o0;
    *reinterpret_cast<float4*>(&out[(size_t)row * D_MODEL + d0 + 4]) = o1;
}

// ---------------------------------------------------------------------------
// Launch
// ---------------------------------------------------------------------------
extern "C" void kernel_launch(void* const* d_in, const int* in_sizes, int n_in,
                              void* d_out, int out_size) {
    const float* x     = (const float*)d_in[0];
    const float* pad   = (const float*)d_in[1];
    const float* Wq    = (const float*)d_in[2];
    const float* bq    = (const float*)d_in[3];
    const float* Wk    = (const float*)d_in[4];
    const float* bk    = (const float*)d_in[5];
    const float* Wv    = (const float*)d_in[6];
    const float* bv    = (const float*)d_in[7];
    const float* gamma = (const float*)d_in[8];
    const float* beta  = (const float*)d_in[9];

    const int N = in_sizes[1];            // pad_mask [B,S] -> N = B*S rows
    const int B = N / S_LEN;
    const int xblocks = N * (D_MODEL / 8) / 256;
    const int mwords  = N / 2;
    const int mblocks = (mwords + 255) / 256;

    static bool attr_set = false;
    if (!attr_set) {
        cudaFuncSetAttribute(qkv_mma_kernel,
                             cudaFuncAttributeMaxDynamicSharedMemorySize, QKV_SMEM);
        attr_set = true;
    }

    convert_kernel<<<xblocks + 384 + mblocks, 256>>>(x, Wq, Wk, Wv, pad, xblocks, mwords);
    qkv_mma_kernel<<<dim3(N / 128, 4, 3), 256, QKV_SMEM>>>(bq, bk, bv);
    attn_mma_kernel<<<dim3(S_LEN / 256, NUM_HEADS, B), 256>>>();
    ln_kernel<<<N / 8, 256>>>(x, gamma, beta, (float*)d_out);
}

// round 14
// speedup vs baseline: 1.1642x; 1.0057x over previous
#include <cuda_runtime.h>
#include <cuda_fp16.h>
#include <math.h>
#include <stdint.h>

#define D_MODEL   256
#define NUM_HEADS 8
#define DIM_HEAD  32
#define S_LEN     4096
#define MAX_B     2
#define LN_EPS    1e-6f
#define FULL_MASK 0xffffffffu
#define QK_SCALE  0.2550565405694324f      // (1/sqrt(32)) * log2(e)

// f16 scratch stored as packed words.
__device__ uint32_t g_xh[MAX_B * S_LEN * D_MODEL / 2];        // [N][128w] f16 x
__device__ uint32_t g_wt[3 * D_MODEL * D_MODEL / 2];          // [z][n][128w] f16 W^T
__device__ uint32_t g_mh[MAX_B * S_LEN / 2];                  // f16x2 mask, [tile][qq][j]
__device__ uint32_t g_q[MAX_B * NUM_HEADS * S_LEN * DIM_HEAD / 2];
__device__ uint32_t g_k[MAX_B * NUM_HEADS * S_LEN * DIM_HEAD / 2];
__device__ uint32_t g_v[MAX_B * NUM_HEADS * S_LEN * DIM_HEAD / 2];
__device__ uint32_t g_o[MAX_B * NUM_HEADS * S_LEN * DIM_HEAD / 2];   // f16 O

// ---------------------------------------------------------------------------
// Helpers
// ---------------------------------------------------------------------------
__device__ __forceinline__ uint32_t pack_f16(float lo, float hi) {
    uint32_t r;
    asm("cvt.rn.f16x2.f32 %0, %1, %2;" : "=r"(r) : "f"(hi), "f"(lo));
    return r;
}
__device__ __forceinline__ uint32_t ex2_f16x2(uint32_t x) {
    uint32_t y;
    asm("ex2.approx.f16x2 %0, %1;" : "=r"(y) : "r"(x));
    return y;
}
__device__ __forceinline__ uint32_t hadd2(uint32_t a, uint32_t b) {
    uint32_t y;
    asm("add.rn.f16x2 %0, %1, %2;" : "=r"(y) : "r"(a), "r"(b));
    return y;
}
__device__ __forceinline__ float2 h2f2(uint32_t w) {
    __half2 h = *reinterpret_cast<__half2*>(&w);
    return __half22float2(h);
}
// f32-accum mma (QKV projection + PV)
__device__ __forceinline__ void mma_f16(float c[4],
                                        uint32_t a0, uint32_t a1, uint32_t a2, uint32_t a3,
                                        uint32_t b0, uint32_t b1) {
    asm volatile(
        "mma.sync.aligned.m16n8k16.row.col.f32.f16.f16.f32 "
        "{%0,%1,%2,%3},{%4,%5,%6,%7},{%8,%9},{%0,%1,%2,%3};"
        : "+f"(c[0]), "+f"(c[1]), "+f"(c[2]), "+f"(c[3])
        : "r"(a0), "r"(a1), "r"(a2), "r"(a3), "r"(b0), "r"(b1));
}
// f16-accum mma (scores): C/D are two f16x2 words
__device__ __forceinline__ void mma_f16h(uint32_t c[2],
                                         uint32_t a0, uint32_t a1, uint32_t a2, uint32_t a3,
                                         uint32_t b0, uint32_t b1) {
    asm volatile(
        "mma.sync.aligned.m16n8k16.row.col.f16.f16.f16.f16 "
        "{%0,%1},{%2,%3,%4,%5},{%6,%7},{%0,%1};"
        : "+r"(c[0]), "+r"(c[1])
        : "r"(a0), "r"(a1), "r"(a2), "r"(a3), "r"(b0), "r"(b1));
}
__device__ __forceinline__ void ldsm_x4(uint32_t& d0, uint32_t& d1,
                                        uint32_t& d2, uint32_t& d3, uint32_t addr) {
    asm volatile("ldmatrix.sync.aligned.m8n8.x4.shared.b16 {%0,%1,%2,%3}, [%4];"
                 : "=r"(d0), "=r"(d1), "=r"(d2), "=r"(d3) : "r"(addr));
}
__device__ __forceinline__ void cp16(uint32_t dst, const void* src) {
    asm volatile("cp.async.cg.shared.global [%0], [%1], 16;" :: "r"(dst), "l"(src));
}
__device__ __forceinline__ void cp_commit() {
    asm volatile("cp.async.commit_group;");
}
__device__ __forceinline__ void cp_wait0() {
    asm volatile("cp.async.wait_group 0;");
}
__device__ __forceinline__ void cp_wait1() {
    asm volatile("cp.async.wait_group 1;");
}

// ---------------------------------------------------------------------------
// Kernel 0: fp32 -> f16 conversion. x -> g_xh; W^T -> g_wt; mask -> g_mh.
// Mask stored permuted per 64-key tile: word index = qq*8 + j.
// ---------------------------------------------------------------------------
__global__ void convert_kernel(const float* __restrict__ x,
                               const float* __restrict__ Wq,
                               const float* __restrict__ Wk,
                               const float* __restrict__ Wv,
                               const float* __restrict__ pad,
                               int xblocks, int mwords) {
    const int bid = blockIdx.x;
    if (bid < xblocks) {
        const int j = bid * 256 + threadIdx.x;
        const float4 f0 = *reinterpret_cast<const float4*>(&x[j * 8]);
        const float4 f1 = *reinterpret_cast<const float4*>(&x[j * 8 + 4]);
        uint4 o;
        o.x = pack_f16(f0.x, f0.y); o.y = pack_f16(f0.z, f0.w);
        o.z = pack_f16(f1.x, f1.y); o.w = pack_f16(f1.z, f1.w);
        reinterpret_cast<uint4*>(g_xh)[j] = o;
    } else if (bid < xblocks + 384) {
        const int i  = (bid - xblocks) * 256 + threadIdx.x;
        const int n  = i & 255;
        const int kw = (i >> 8) & 127;
        const int z  = i >> 15;
        const float* W = (z == 0) ? Wq : (z == 1) ? Wk : Wv;
        const float a = W[(2 * kw    ) * D_MODEL + n];
        const float b = W[(2 * kw + 1) * D_MODEL + n];
        g_wt[z * 32768 + n * 128 + kw] = pack_f16(a, b);
    } else {
        const int w = (bid - xblocks - 384) * 256 + threadIdx.x;
        if (w < mwords) {
            const float2 m = *reinterpret_cast<const float2*>(&pad[w * 2]);
            const uint32_t lo = (m.x > 0.5f) ? 0xFC00u : 0u;
            const uint32_t hi = (m.y > 0.5f) ? 0xFC00u : 0u;
            const int tile = w >> 5;
            const int pair = w & 31;
            const int jj   = pair >> 2;
            const int qq2  = pair & 3;
            g_mh[tile * 32 + qq2 * 8 + jj] = lo | (hi << 16);
        }
    }
}

// ---------------------------------------------------------------------------
// Kernel 1: QKV projection, f16 mma, cp.async double-buffer, ldmatrix frags.
// grid = (N/128, 4, 3), block = 256 (8 warps: 4 m x 2 n).
// ---------------------------------------------------------------------------
#define AS_WORDS (128 * 36)
#define WS_WORDS (64 * 36)
#define QKV_SMEM ((2 * AS_WORDS + 2 * WS_WORDS) * 4)

__global__ void __launch_bounds__(256, 2)
qkv_mma_kernel(const float* __restrict__ bq, const float* __restrict__ bk,
               const float* __restrict__ bv) {
    extern __shared__ __align__(16) uint32_t dsm[];
    uint32_t* AsW = dsm;
    uint32_t* WsW = dsm + 2 * AS_WORDS;

    const int z = blockIdx.z;
    const float* bias = (z == 0) ? bq : (z == 1) ? bk : bv;

    const int row0 = blockIdx.x * 128;
    const int n0   = blockIdx.y * 64;
    const int tid  = threadIdx.x;
    const int warp = tid >> 5, lane = tid & 31;
    const int r    = lane >> 2, qq = lane & 3;
    const int wm   = warp >> 1;
    const int wn   = warp & 1;

    const uint32_t as_st = (uint32_t)__cvta_generic_to_shared(AsW);
    const uint32_t ws_st = (uint32_t)__cvta_generic_to_shared(WsW);
    const uint32_t AS_B = AS_WORDS * 4, WS_B = WS_WORDS * 4;

    const uint32_t* xsrc = g_xh + (size_t)row0 * 128;
    const uint32_t* wsrc = g_wt + z * 32768 + n0 * 128;

    auto issue_chunk = [&](int kc) {
        const int buf = kc & 1;
        #pragma unroll
        for (int i = 0; i < 4; i++) {
            const int idx = tid + i * 256;
            const int m = idx >> 3, q = idx & 7;
            cp16(as_st + buf * AS_B + (m * 36 + q * 4) * 4,
                 xsrc + m * 128 + kc * 32 + q * 4);
        }
        #pragma unroll
        for (int i = 0; i < 2; i++) {
            const int idx = tid + i * 256;
            const int n = idx >> 3, q = idx & 7;
            cp16(ws_st + buf * WS_B + (n * 36 + q * 4) * 4,
                 wsrc + n * 128 + kc * 32 + q * 4);
        }
        cp_commit();
    };

    float acc[2][4][4];
    #pragma unroll
    for (int mf = 0; mf < 2; mf++)
        #pragma unroll
        for (int nf = 0; nf < 4; nf++)
            #pragma unroll
            for (int i = 0; i < 4; i++) acc[mf][nf][i] = 0.f;

    const uint32_t a_lane = ((wm * 32 + (lane & 15)) * 36 + (lane >> 4) * 4) * 4;
    const uint32_t b_lane = ((wn * 32 + (lane & 15)) * 36 + (lane >> 4) * 4) * 4;

    issue_chunk(0);
    for (int kc = 0; kc < 4; kc++) {
        cp_wait0();
        __syncthreads();
        if (kc < 3) issue_chunk(kc + 1);

        const int buf = kc & 1;
        const uint32_t ab = as_st + buf * AS_B + a_lane;
        const uint32_t bb = ws_st + buf * WS_B + b_lane;
        #pragma unroll
        for (int ks = 0; ks < 4; ks++) {
            uint32_t a[2][4], bf[4][2];
            ldsm_x4(a[0][0], a[0][1], a[0][2], a[0][3], ab + ks * 32);
            ldsm_x4(a[1][0], a[1][1], a[1][2], a[1][3], ab + 16 * 36 * 4 + ks * 32);
            ldsm_x4(bf[0][0], bf[1][0], bf[0][1], bf[1][1], bb + ks * 32);
            ldsm_x4(bf[2][0], bf[3][0], bf[2][1], bf[3][1], bb + 16 * 36 * 4 + ks * 32);
            #pragma unroll
            for (int mf = 0; mf < 2; mf++)
                #pragma unroll
                for (int nf = 0; nf < 4; nf++)
                    mma_f16(acc[mf][nf], a[mf][0], a[mf][1], a[mf][2], a[mf][3],
                            bf[nf][0], bf[nf][1]);
        }
        if (kc < 3) __syncthreads();
    }

    const int b  = row0 >> 12;
    const int s0 = row0 & (S_LEN - 1);

    if (z != 2) {
        uint32_t* out = (z == 0) ? g_q : g_k;
        const float scale = (z == 0) ? QK_SCALE : 1.0f;
        const int h  = (n0 >> 5) + wn;
        const int bh = b * NUM_HEADS + h;
        #pragma unroll
        for (int mf = 0; mf < 2; mf++) {
            const int s = s0 + wm * 32 + mf * 16;
            #pragma unroll
            for (int nf = 0; nf < 4; nf++) {
                const float2 bb = *reinterpret_cast<const float2*>(
                    &bias[n0 + wn * 32 + nf * 8 + qq * 2]);
                const float c0 = (acc[mf][nf][0] + bb.x) * scale;
                const float c1 = (acc[mf][nf][1] + bb.y) * scale;
                const float c2 = (acc[mf][nf][2] + bb.x) * scale;
                const float c3 = (acc[mf][nf][3] + bb.y) * scale;
                out[((size_t)bh * S_LEN + s + r    ) * 16 + nf * 4 + qq] = pack_f16(c0, c1);
                out[((size_t)bh * S_LEN + s + r + 8) * 16 + nf * 4 + qq] = pack_f16(c2, c3);
            }
        }
    } else {
        __syncthreads();
        __half* Vt = reinterpret_cast<__half*>(dsm);   // [64 n][136 s]
        #pragma unroll
        for (int mf = 0; mf < 2; mf++) {
            const int ml = wm * 32 + mf * 16;
            #pragma unroll
            for (int nf = 0; nf < 4; nf++) {
                const int nc = wn * 32 + nf * 8 + qq * 2;
                const float2 bb = *reinterpret_cast<const float2*>(&bias[n0 + nc]);
                Vt[(nc    ) * 136 + ml + r    ] = __float2half(acc[mf][nf][0] + bb.x);
                Vt[(nc + 1) * 136 + ml + r    ] = __float2half(acc[mf][nf][1] + bb.y);
                Vt[(nc    ) * 136 + ml + r + 8] = __float2half(acc[mf][nf][2] + bb.x);
                Vt[(nc + 1) * 136 + ml + r + 8] = __float2half(acc[mf][nf][3] + bb.y);
            }
        }
        __syncthreads();
        #pragma unroll
        for (int i = 0; i < 4; i++) {
            const int idx = tid + i * 256;
            const int n = idx >> 4, wq = (idx & 15) * 4;
            const uint4 val = *reinterpret_cast<const uint4*>(&Vt[n * 136 + wq * 2]);
            const int col = n0 + n;
            const int bh  = b * NUM_HEADS + (col >> 5);
            const int dh  = col & 31;
            *reinterpret_cast<uint4*>(
                &g_v[((size_t)bh * DIM_HEAD + dh) * (S_LEN / 2) + (s0 >> 1) + wq]) = val;
        }
    }
}

// ---------------------------------------------------------------------------
// Kernel 2: flash attention, 32 q-rows per warp (BQ=256). (R13 winner, frozen)
// grid = (S/256, H, B), block = 256 (8 warps).
// ---------------------------------------------------------------------------
__global__ void __launch_bounds__(256, 2)
attn_mma_kernel() {
    __shared__ __align__(16) uint32_t Ks[3][64][20];
    __shared__ __align__(16) uint32_t Vs[3][32][36];
    __shared__ __align__(16) uint32_t Ms[3][32];     // f16x2 mask, [qq][j] order

    const int tid  = threadIdx.x;
    const int warp = tid >> 5;
    const int lane = tid & 31;
    const int r    = lane >> 2;
    const int qq   = lane & 3;

    const int qt = blockIdx.x, h = blockIdx.y, b = blockIdx.z;
    const int bh = b * NUM_HEADS + h;
    const int q0 = qt * 256 + warp * 32;

    const uint32_t ks_st = (uint32_t)__cvta_generic_to_shared(&Ks[0][0][0]);
    const uint32_t vs_st = (uint32_t)__cvta_generic_to_shared(&Vs[0][0][0]);
    const uint32_t ms_st = (uint32_t)__cvta_generic_to_shared(&Ms[0][0]);
    const uint32_t KS_B = 64 * 20 * 4, VS_B = 32 * 36 * 4;

    const uint32_t ks_lane = (uint32_t)__cvta_generic_to_shared(
        &Ks[0][lane & 7][(lane >> 3) * 4]);
    const uint32_t vs_lane = (uint32_t)__cvta_generic_to_shared(
        &Vs[0][lane & 7][(lane >> 3) * 4]);

    const uint32_t* Kw = g_k + (size_t)bh * S_LEN * 16;
    const uint32_t* Vw = g_v + (size_t)bh * DIM_HEAD * (S_LEN / 2);
    const uint32_t* Mw = g_mh + b * (S_LEN / 2);

    auto issue_tile = [&](int t) {
        const int buf = t % 3;
        cp16(ks_st + buf * KS_B + ((tid >> 2) * 20 + (tid & 3) * 4) * 4,
             Kw + t * 1024 + tid * 4);
        cp16(vs_st + buf * VS_B + ((tid >> 3) * 36 + (tid & 7) * 4) * 4,
             Vw + (tid >> 3) * (S_LEN / 2) + t * 32 + (tid & 7) * 4);
        if (tid < 8) cp16(ms_st + buf * 128 + tid * 16, Mw + t * 32 + tid * 4);
        cp_commit();
    };

    // Q fragments: 2 m-frags (rows q0+mf*16), 2 k-chunks each (pre-scaled)
    uint32_t qa[2][2][4];
    {
        const uint32_t* Qw = g_q + ((size_t)bh * S_LEN + q0) * 16;
        #pragma unroll
        for (int mf = 0; mf < 2; mf++)
            #pragma unroll
            for (int t = 0; t < 2; t++) {
                qa[mf][t][0] = Qw[(mf * 16 + r    ) * 16 + t * 8 + qq    ];
                qa[mf][t][1] = Qw[(mf * 16 + r + 8) * 16 + t * 8 + qq    ];
                qa[mf][t][2] = Qw[(mf * 16 + r    ) * 16 + t * 8 + qq + 4];
                qa[mf][t][3] = Qw[(mf * 16 + r + 8) * 16 + t * 8 + qq + 4];
            }
    }

    float oa[2][4][4];
    #pragma unroll
    for (int mf = 0; mf < 2; mf++)
        #pragma unroll
        for (int nn = 0; nn < 4; nn++)
            #pragma unroll
            for (int i = 0; i < 4; i++) oa[mf][nn][i] = 0.f;
    float l[2][2] = {{0.f, 0.f}, {0.f, 0.f}};

    issue_tile(0);
    issue_tile(1);

    for (int kt = 0; kt < S_LEN / 64; kt++) {
        if (kt < S_LEN / 64 - 1) cp_wait1(); else cp_wait0();
        __syncthreads();
        if (kt + 2 < S_LEN / 64) issue_tile(kt + 2);

        const int p = kt % 3;
        const uint32_t kaddr = ks_lane + (uint32_t)p * KS_B;
        const uint32_t vaddr = vs_lane + (uint32_t)p * VS_B;

        const uint4 m03 = *reinterpret_cast<const uint4*>(&Ms[p][qq * 8]);
        const uint4 m47 = *reinterpret_cast<const uint4*>(&Ms[p][qq * 8 + 4]);
        const uint32_t mw[8] = {m03.x, m03.y, m03.z, m03.w,
                                m47.x, m47.y, m47.z, m47.w};

        // ---- scores: each K ldsm feeds BOTH m-frags ----
        uint32_t pa[2][4][4];
        #pragma unroll
        for (int j = 0; j < 8; j++) {
            uint32_t b00, b01, b10, b11;
            ldsm_x4(b00, b01, b10, b11, kaddr + j * (8 * 20 * 4));
            #pragma unroll
            for (int mf = 0; mf < 2; mf++) {
                uint32_t sd[2] = {mw[j], mw[j]};
                mma_f16h(sd, qa[mf][0][0], qa[mf][0][1], qa[mf][0][2], qa[mf][0][3], b00, b01);
                mma_f16h(sd, qa[mf][1][0], qa[mf][1][1], qa[mf][1][2], qa[mf][1][3], b10, b11);
                pa[mf][j >> 1][(j & 1) * 2    ] = ex2_f16x2(sd[0]);
                pa[mf][j >> 1][(j & 1) * 2 + 1] = ex2_f16x2(sd[1]);
            }
        }

        // ---- l: hadd2 trees, f32 accumulate ----
        #pragma unroll
        for (int mf = 0; mf < 2; mf++) {
            const uint32_t t0 = hadd2(
                hadd2(hadd2(pa[mf][0][0], pa[mf][0][2]), hadd2(pa[mf][1][0], pa[mf][1][2])),
                hadd2(hadd2(pa[mf][2][0], pa[mf][2][2]), hadd2(pa[mf][3][0], pa[mf][3][2])));
            const uint32_t t1 = hadd2(
                hadd2(hadd2(pa[mf][0][1], pa[mf][0][3]), hadd2(pa[mf][1][1], pa[mf][1][3])),
                hadd2(hadd2(pa[mf][2][1], pa[mf][2][3]), hadd2(pa[mf][3][1], pa[mf][3][3])));
            const float2 f0 = h2f2(t0);
            const float2 f1 = h2f2(t1);
            l[mf][0] += f0.x + f0.y;
            l[mf][1] += f1.x + f1.y;
        }

        // ---- PV: each V ldsm feeds BOTH m-frags ----
        #pragma unroll
        for (int nn = 0; nn < 4; nn++) {
            uint32_t vb[4][2];
            ldsm_x4(vb[0][0], vb[0][1], vb[1][0], vb[1][1],
                    vaddr + nn * (8 * 36 * 4));
            ldsm_x4(vb[2][0], vb[2][1], vb[3][0], vb[3][1],
                    vaddr + nn * (8 * 36 * 4) + 64);
            #pragma unroll
            for (int mf = 0; mf < 2; mf++)
                #pragma unroll
                for (int jp = 0; jp < 4; jp++)
                    mma_f16(oa[mf][nn], pa[mf][jp][0], pa[mf][jp][1],
                            pa[mf][jp][2], pa[mf][jp][3], vb[jp][0], vb[jp][1]);
        }
    }

    // quad reductions + store
    uint32_t* Op = g_o + ((size_t)bh * S_LEN + q0) * 16;
    #pragma unroll
    for (int mf = 0; mf < 2; mf++) {
        float l0 = l[mf][0], l1 = l[mf][1];
        l0 += __shfl_xor_sync(FULL_MASK, l0, 1);
        l0 += __shfl_xor_sync(FULL_MASK, l0, 2);
        l1 += __shfl_xor_sync(FULL_MASK, l1, 1);
        l1 += __shfl_xor_sync(FULL_MASK, l1, 2);
        const float i0 = 1.0f / l0;
        const float i1 = 1.0f / l1;
        #pragma unroll
        for (int nn = 0; nn < 4; nn++) {
            Op[(mf * 16 + r    ) * 16 + nn * 4 + qq] =
                pack_f16(oa[mf][nn][0] * i0, oa[mf][nn][1] * i0);
            Op[(mf * 16 + r + 8) * 16 + nn * 4 + qq] =
                pack_f16(oa[mf][nn][2] * i1, oa[mf][nn][3] * i1);
        }
    }
}

// ---------------------------------------------------------------------------
// Kernel 3: residual + LayerNorm, 4 rows per warp with front-batched loads
// (MLP ~12 to hide DRAM latency). grid = N/32, block = 256 (8 warps).
// ---------------------------------------------------------------------------
__global__ void ln_kernel(const float* __restrict__ x,
                          const float* __restrict__ gamma,
                          const float* __restrict__ beta,
                          float* __restrict__ out) {
    const int warp = threadIdx.x >> 5;
    const int lane = threadIdx.x & 31;
    const int row0 = blockIdx.x * 32 + warp * 4;   // 4 consecutive rows
    const int b    = row0 >> 12;                   // same batch (4096 % 32 == 0)
    const int s0   = row0 & (S_LEN - 1);

    const int d0 = lane * 8;
    const int bh = b * NUM_HEADS + (d0 >> 5);
    const uint32_t* Oq = &g_o[((size_t)bh * S_LEN + s0) * 16 + (lane & 3) * 4];
    const float* Xq = &x[(size_t)row0 * D_MODEL + d0];

    // front-batched loads: 4 rows x (1 uint4 from g_o + 2 float4 from x)
    uint4  aw[4];
    float4 x0[4], x1[4];
    #pragma unroll
    for (int rr = 0; rr < 4; rr++) {
        aw[rr] = *reinterpret_cast<const uint4*>(Oq + rr * 16);
        x0[rr] = *reinterpret_cast<const float4*>(Xq + rr * D_MODEL);
        x1[rr] = *reinterpret_cast<const float4*>(Xq + rr * D_MODEL + 4);
    }

    const float4 g0 = *reinterpret_cast<const float4*>(&gamma[d0]);
    const float4 g1 = *reinterpret_cast<const float4*>(&gamma[d0 + 4]);
    const float4 b0 = *reinterpret_cast<const float4*>(&beta[d0]);
    const float4 b1 = *reinterpret_cast<const float4*>(&beta[d0 + 4]);

    #pragma unroll
    for (int rr = 0; rr < 4; rr++) {
        const float2 a0 = __half22float2(*reinterpret_cast<const __half2*>(&aw[rr].x));
        const float2 a1 = __half22float2(*reinterpret_cast<const __half2*>(&aw[rr].y));
        const float2 a2 = __half22float2(*reinterpret_cast<const __half2*>(&aw[rr].z));
        const float2 a3 = __half22float2(*reinterpret_cast<const __half2*>(&aw[rr].w));
        float v[8];
        v[0] = a0.x + x0[rr].x; v[1] = a0.y + x0[rr].y;
        v[2] = a1.x + x0[rr].z; v[3] = a1.y + x0[rr].w;
        v[4] = a2.x + x1[rr].x; v[5] = a2.y + x1[rr].y;
        v[6] = a3.x + x1[rr].z; v[7] = a3.y + x1[rr].w;

        float sum = 0.f, sq = 0.f;
        #pragma unroll
        for (int i = 0; i < 8; i++) { sum += v[i]; sq += v[i] * v[i]; }
        #pragma unroll
        for (int off = 16; off > 0; off >>= 1) {
            sum += __shfl_xor_sync(FULL_MASK, sum, off);
            sq  += __shfl_xor_sync(FULL_MASK, sq,  off);
        }
        const float mu  = sum * (1.0f / D_MODEL);
        const float var = sq * (1.0f / D_MODEL) - mu * mu;
        const float rs  = rsqrtf(var + LN_EPS);

        float4 o0, o1;
        o0.x = g0.x * (v[0] - mu) * rs + b0.x;
        o0.y = g0.y * (v[1] - mu) * rs + b0.y;
        o0.z = g0.z * (v[2] - mu) * rs + b0.z;
        o0.w = g0.w * (v[3] - mu) * rs + b0.w;
        o1.x = g1.x * (v[4] - mu) * rs + b1.x;
        o1.y = g1.y * (v[5] - mu) * rs + b1.y;
        o1.z = g1.z * (v[6] - mu) * rs + b1.z;
        o1.w = g1.w * (v[7] - mu) * rs + b1.w;
        *reinterpret_cast<float4*>(&out[(size_t)(row0 + rr) * D_MODEL + d0])     = o0;
        *reinterpret_cast<float4*>(&out[(size_t)(row0 + rr) * D_MODEL + d0 + 4]) = o1;
    }
}

// ---------------------------------------------------------------------------
// Launch
// ---------------------------------------------------------------------------
extern "C" void kernel_launch(void* const* d_in, const int* in_sizes, int n_in,
                              void* d_out, int out_size) {
    const float* x     = (const float*)d_in[0];
    const float* pad   = (const float*)d_in[1];
    const float* Wq    = (const float*)d_in[2];
    const float* bq    = (const float*)d_in[3];
    const float* Wk    = (const float*)d_in[4];
    const float* bk    = (const float*)d_in[5];
    const float* Wv    = (const float*)d_in[6];
    const float* bv    = (const float*)d_in[7];
    const float* gamma = (const float*)d_in[8];
    const float* beta  = (const float*)d_in[9];

    const int N = in_sizes[1];            // pad_mask [B,S] -> N = B*S rows
    const int B = N / S_LEN;
    const int xblocks = N * (D_MODEL / 8) / 256;
    const int mwords  = N / 2;
    const int mblocks = (mwords + 255) / 256;

    static bool attr_set = false;
    if (!attr_set) {
        cudaFuncSetAttribute(qkv_mma_kernel,
                             cudaFuncAttributeMaxDynamicSharedMemorySize, QKV_SMEM);
        attr_set = true;
    }

    convert_kernel<<<xblocks + 384 + mblocks, 256>>>(x, Wq, Wk, Wv, pad, xblocks, mwords);
    qkv_mma_kernel<<<dim3(N / 128, 4, 3), 256, QKV_SMEM>>>(bq, bk, bv);
    attn_mma_kernel<<<dim3(S_LEN / 256, NUM_HEADS, B), 256>>>();
    ln_kernel<<<N / 32, 256>>>(x, gamma, beta, (float*)d_out);
}